// round 2
// baseline (speedup 1.0000x reference)
#include <cuda_runtime.h>

// Segment mean pooling:
//   out[s, :] = sum_{i : ids[i]==s} data[i, :] / count(s)
// N = 4,000,000 rows, D = 64 fp32, S = 100,000 segments.
//
// Strategy: L2-resident scatter-add with vectorized red.global.add.v4.f32,
// then in-place divide by per-segment counts.
// Robustness: inputs identified by element count (not position); segment-id
// dtype (int64 vs int32) detected on device from the first 256 values.

#define SEG_MAX 100000
#define D_DIM 64

__device__ float g_counts[SEG_MAX];
__device__ int   g_ids_is_i32;   // 0 = int64 layout, 1 = int32 layout

// Kernel 1: zero the accumulator (d_out), the counts array, and the mode flag.
__global__ void zero_kernel(float4* __restrict__ out4, int n_out4) {
    int i = blockIdx.x * blockDim.x + threadIdx.x;
    if (i < n_out4) {
        out4[i] = make_float4(0.f, 0.f, 0.f, 0.f);
    }
    if (i < SEG_MAX) {
        g_counts[i] = 0.f;
    }
    if (i == 0) {
        g_ids_is_i32 = 0;
    }
}

// Kernel 2: detect ids dtype. Under the int64 interpretation, every valid id
// is in [0, SEG_MAX). If ids are actually int32, an int64 read combines two
// ids: lo + hi*2^32, which is out of range unless hi == 0 (P = 1e-5 per slot;
// all-256 ≈ impossible).
__global__ void detect_kernel(const long long* __restrict__ ids64) {
    long long v = ids64[threadIdx.x];
    if (v < 0 || v >= (long long)SEG_MAX) {
        atomicOr(&g_ids_is_i32, 1);
    }
}

// Kernel 3: scatter-add. One thread per (row, 16B chunk): 16 threads/row.
// Consecutive threads read consecutive float4 -> fully coalesced data reads.
__global__ void scatter_kernel(const float4* __restrict__ data4,
                               const void* __restrict__ ids_raw,
                               float* __restrict__ sum,
                               int n_items) {
    int i = blockIdx.x * blockDim.x + threadIdx.x;
    if (i >= n_items) return;

    int row   = i >> 4;   // i / 16
    int chunk = i & 15;   // 16B chunk within the 256B row

    int seg;
    if (g_ids_is_i32) {
        seg = __ldg(((const int*)ids_raw) + row);
    } else {
        seg = (int)__ldg(((const long long*)ids_raw) + row);
    }

    float4 v = __ldg(&data4[i]);

    float* dst = sum + ((long long)seg << 6) + (chunk << 2);
    asm volatile("red.global.add.v4.f32 [%0], {%1, %2, %3, %4};"
                 :: "l"(dst), "f"(v.x), "f"(v.y), "f"(v.z), "f"(v.w)
                 : "memory");

    if (chunk == 0) {
        atomicAdd(&g_counts[seg], 1.0f);
    }
}

// Kernel 4: in-place divide by counts. 16 float4 per row -> count idx = i>>4.
__global__ void divide_kernel(float4* __restrict__ out4, int n_out4) {
    int i = blockIdx.x * blockDim.x + threadIdx.x;
    if (i >= n_out4) return;

    float c = g_counts[i >> 4];
    float inv = 1.0f / c;

    float4 v = out4[i];
    v.x *= inv; v.y *= inv; v.z *= inv; v.w *= inv;
    out4[i] = v;
}

extern "C" void kernel_launch(void* const* d_in, const int* in_sizes, int n_in,
                              void* d_out, int out_size) {
    // Identify inputs by element count, not position:
    //   data: largest element count (N*D = 256M)
    //   ids : element count == N (data_count / 64)
    int data_idx = 0;
    long long best = -1;
    for (int i = 0; i < n_in; i++) {
        if ((long long)in_sizes[i] > best) { best = in_sizes[i]; data_idx = i; }
    }
    long long n_rows = best / D_DIM;

    int ids_idx = -1;
    for (int i = 0; i < n_in; i++) {
        if (i != data_idx && (long long)in_sizes[i] == n_rows) { ids_idx = i; break; }
    }
    if (ids_idx < 0) {
        // Fallback: any other non-scalar input
        for (int i = 0; i < n_in; i++) {
            if (i != data_idx && in_sizes[i] > 1) { ids_idx = i; break; }
        }
    }

    const float* data = (const float*)d_in[data_idx];
    const void*  ids  = d_in[ids_idx];
    float* out = (float*)d_out;

    int n_items = (int)(n_rows * (D_DIM / 4));   // N * 16 = 64M float4 chunks
    int n_out4  = out_size / 4;                  // S * 16 = 1.6M float4

    const int TPB = 256;

    // 1. Zero accumulator + counts + flag
    int zero_blocks = (n_out4 + TPB - 1) / TPB;
    zero_kernel<<<zero_blocks, TPB>>>((float4*)out, n_out4);

    // 2. Detect ids dtype (1 block; stream-ordered after zero)
    detect_kernel<<<1, 256>>>((const long long*)ids);

    // 3. Scatter-add
    int scat_blocks = (n_items + TPB - 1) / TPB;
    scatter_kernel<<<scat_blocks, TPB>>>((const float4*)data, ids, out, n_items);

    // 4. Divide by counts
    int div_blocks = (n_out4 + TPB - 1) / TPB;
    divide_kernel<<<div_blocks, TPB>>>((float4*)out, n_out4);
}